// round 5
// baseline (speedup 1.0000x reference)
#include <cuda_runtime.h>
#include <math.h>

#define T_TOK   32768
#define D_DIM   512
#define E_EXP   16
#define TOPK    2
#define M_DIM   1024
#define CAP     (T_TOK * TOPK)          // 65536 bucket slots
#define BM      64
#define BN      64
#define BK      16
#define MAX_TILES (CAP / BM + E_EXP)    // 1040

// ---------------- scratch (static device memory; no allocs) ----------------
__device__ int   g_top_idx[CAP];
__device__ float g_top_w[CAP];
__device__ int   g_counts[E_EXP];
__device__ int   g_offsets[E_EXP + 1];
__device__ int   g_fill[E_EXP];
__device__ int   g_btok[CAP];
__device__ float g_bw[CAP];
__device__ int   g_tile_e[MAX_TILES];
__device__ int   g_tile_row[MAX_TILES];
__device__ int   g_ntiles;
// padded by one full BM tile so any clamped/stale staging read stays in-bounds
__device__ float g_h[(size_t)(CAP + BM) * M_DIM];

// ---------------- zero kernels (graph-capturable, deterministic) -----------
__global__ void zero_out_kernel(float4* out, int n4) {
    int stride = gridDim.x * blockDim.x;
    for (int i = blockIdx.x * blockDim.x + threadIdx.x; i < n4; i += stride)
        out[i] = make_float4(0.f, 0.f, 0.f, 0.f);
}

__global__ void zero_meta_kernel() {
    int t = threadIdx.x;
    if (t < E_EXP) { g_counts[t] = 0; g_fill[t] = 0; }
}

// ---------------- gating: logits, top-2, softmax ---------------------------
__global__ void gate_kernel(const float* __restrict__ x,
                            const float* __restrict__ wg) {
    __shared__ float s_wg[D_DIM * 17];   // padded stride 17 (bank-conflict-free)
    int tid = threadIdx.x;
    for (int i = tid; i < D_DIM * E_EXP; i += blockDim.x)
        s_wg[(i >> 4) * 17 + (i & 15)] = wg[i];
    __syncthreads();

    int warp = tid >> 5, lane = tid & 31;
    int tok = blockIdx.x * 8 + warp;
    if (tok >= T_TOK) return;

    float acc[E_EXP];
#pragma unroll
    for (int e = 0; e < E_EXP; e++) acc[e] = 0.f;

    const float* xr = x + (size_t)tok * D_DIM;
    for (int d = lane; d < D_DIM; d += 32) {
        float xv = xr[d];
        const float* wrow = &s_wg[d * 17];
#pragma unroll
        for (int e = 0; e < E_EXP; e++) acc[e] += xv * wrow[e];
    }
#pragma unroll
    for (int e = 0; e < E_EXP; e++) {
#pragma unroll
        for (int o = 16; o > 0; o >>= 1)
            acc[e] += __shfl_xor_sync(0xffffffffu, acc[e], o);
    }
    if (lane == 0) {
        int i0 = -1, i1 = -1;
        float v0 = -INFINITY, v1 = -INFINITY;
#pragma unroll
        for (int e = 0; e < E_EXP; e++) {
            float v = acc[e];
            if (v > v0) { v1 = v0; i1 = i0; v0 = v; i0 = e; }
            else if (v > v1) { v1 = v; i1 = e; }
        }
        float e1 = expf(v1 - v0);            // v0 is max
        float inv = 1.f / (1.f + e1);
        g_top_idx[tok * 2]     = i0;
        g_top_idx[tok * 2 + 1] = i1;
        g_top_w[tok * 2]       = inv;
        g_top_w[tok * 2 + 1]   = e1 * inv;
    }
}

// ---------------- bucket build --------------------------------------------
__global__ void count_kernel() {
    int i = blockIdx.x * blockDim.x + threadIdx.x;
    if (i < CAP) atomicAdd(&g_counts[g_top_idx[i]], 1);
}

__global__ void scan_kernel() {
    int s = 0, t = 0;
    for (int e = 0; e < E_EXP; e++) {
        g_offsets[e] = s;
        int c = g_counts[e];
        for (int r = 0; r < c; r += BM) { g_tile_e[t] = e; g_tile_row[t] = r; t++; }
        s += c;
    }
    g_offsets[E_EXP] = s;
    g_ntiles = t;
}

__global__ void scatter_kernel() {
    int i = blockIdx.x * blockDim.x + threadIdx.x;
    if (i < CAP) {
        int e = g_top_idx[i];
        int pos = atomicAdd(&g_fill[e], 1);
        int dst = g_offsets[e] + pos;
        g_btok[dst] = i >> 1;
        g_bw[dst]   = g_top_w[i];
    }
}

// ---------------- GEMM1: h = silu(X @ w0) * (X @ w1), gathered X ----------
__global__ void __launch_bounds__(256) gemm1_kernel(
        const float* __restrict__ x,
        const float* __restrict__ w0,
        const float* __restrict__ w1) {
    if ((int)blockIdx.x >= g_ntiles) return;
    int e    = g_tile_e[blockIdx.x];
    int off  = g_offsets[e];
    int n_e  = g_offsets[e + 1] - off;
    int row0 = g_tile_row[blockIdx.x];
    int col0 = blockIdx.y * BN;

    __shared__ float sX[BK][BM];
    __shared__ float sW0[BK][BN];
    __shared__ float sW1[BK][BN];
    __shared__ int   sTok[BM];

    int tid = threadIdx.x;
    if (tid < BM) {
        int r = row0 + tid;
        sTok[tid] = g_btok[off + (r < n_e ? r : 0)];   // clamp: safe gather
    }
    __syncthreads();

    const float* W0b = w0 + (size_t)e * D_DIM * M_DIM + col0;
    const float* W1b = w1 + (size_t)e * D_DIM * M_DIM + col0;

    float a0[4][4], a1[4][4];
#pragma unroll
    for (int i = 0; i < 4; i++)
#pragma unroll
        for (int j = 0; j < 4; j++) { a0[i][j] = 0.f; a1[i][j] = 0.f; }

    int ty = tid >> 4, tx = tid & 15;

    for (int k0 = 0; k0 < D_DIM; k0 += BK) {
#pragma unroll
        for (int it = 0; it < 4; it++) {
            int elem = tid + it * 256;
            int r  = elem >> 4;
            int kk = elem & 15;
            sX[kk][r] = x[(size_t)sTok[r] * D_DIM + k0 + kk];
        }
#pragma unroll
        for (int it = 0; it < 4; it++) {
            int elem = tid + it * 256;
            int kk = elem >> 6;
            int n  = elem & 63;
            sW0[kk][n] = W0b[(size_t)(k0 + kk) * M_DIM + n];
            sW1[kk][n] = W1b[(size_t)(k0 + kk) * M_DIM + n];
        }
        __syncthreads();
#pragma unroll
        for (int kk = 0; kk < BK; kk++) {
            float av[4], b0v[4], b1v[4];
#pragma unroll
            for (int i = 0; i < 4; i++) av[i] = sX[kk][ty * 4 + i];
#pragma unroll
            for (int j = 0; j < 4; j++) { b0v[j] = sW0[kk][tx * 4 + j]; b1v[j] = sW1[kk][tx * 4 + j]; }
#pragma unroll
            for (int i = 0; i < 4; i++)
#pragma unroll
                for (int j = 0; j < 4; j++) {
                    a0[i][j] += av[i] * b0v[j];
                    a1[i][j] += av[i] * b1v[j];
                }
        }
        __syncthreads();
    }

#pragma unroll
    for (int i = 0; i < 4; i++) {
        int r = ty * 4 + i;
        if (row0 + r < n_e) {
            size_t grow = (size_t)(off + row0 + r) * M_DIM + col0;
#pragma unroll
            for (int j = 0; j < 4; j++) {
                float u = a0[i][j];
                float h = (u / (1.f + expf(-u))) * a1[i][j];
                g_h[grow + tx * 4 + j] = h;
            }
        }
    }
}

// ---------------- GEMM2: out += weight * (h @ wo) -------------------------
__global__ void __launch_bounds__(256) gemm2_kernel(
        const float* __restrict__ wo,
        float* __restrict__ out) {
    if ((int)blockIdx.x >= g_ntiles) return;
    int e    = g_tile_e[blockIdx.x];
    int off  = g_offsets[e];
    int n_e  = g_offsets[e + 1] - off;
    int row0 = g_tile_row[blockIdx.x];
    int col0 = blockIdx.y * BN;

    __shared__ float sH[BK][BM];
    __shared__ float sW[BK][BN];
    __shared__ int   sTok[BM];
    __shared__ float sWt[BM];

    int tid = threadIdx.x;
    if (tid < BM) {
        int r = row0 + tid;
        int src = off + (r < n_e ? r : 0);
        sTok[tid] = g_btok[src];
        sWt[tid]  = g_bw[src];
    }
    __syncthreads();

    const float* Wb = wo + (size_t)e * M_DIM * D_DIM + col0;
    const float* Hb = g_h + (size_t)(off + row0) * M_DIM;
    int rows_in_tile = n_e - row0;   // valid rows this tile (>=1)

    float acc[4][4];
#pragma unroll
    for (int i = 0; i < 4; i++)
#pragma unroll
        for (int j = 0; j < 4; j++) acc[i][j] = 0.f;

    int ty = tid >> 4, tx = tid & 15;

    for (int k0 = 0; k0 < M_DIM; k0 += BK) {
#pragma unroll
        for (int it = 0; it < 4; it++) {
            int elem = tid + it * 256;
            int r  = elem >> 4;
            int kk = elem & 15;
            // CLAMP: out-of-range rows of the LAST expert's final tile would
            // otherwise read past the end of g_h (the round-0 illegal access).
            int rs = (r < rows_in_tile) ? r : 0;
            sH[kk][r] = Hb[(size_t)rs * M_DIM + k0 + kk];
        }
#pragma unroll
        for (int it = 0; it < 4; it++) {
            int elem = tid + it * 256;
            int kk = elem >> 6;
            int n  = elem & 63;
            sW[kk][n] = Wb[(size_t)(k0 + kk) * D_DIM + n];
        }
        __syncthreads();
#pragma unroll
        for (int kk = 0; kk < BK; kk++) {
            float av[4], bv[4];
#pragma unroll
            for (int i = 0; i < 4; i++) av[i] = sH[kk][ty * 4 + i];
#pragma unroll
            for (int j = 0; j < 4; j++) bv[j] = sW[kk][tx * 4 + j];
#pragma unroll
            for (int i = 0; i < 4; i++)
#pragma unroll
                for (int j = 0; j < 4; j++) acc[i][j] += av[i] * bv[j];
        }
        __syncthreads();
    }

#pragma unroll
    for (int i = 0; i < 4; i++) {
        int r = ty * 4 + i;
        if (r < rows_in_tile) {
            float wt = sWt[r];
            float* orow = out + (size_t)sTok[r] * D_DIM + col0;
#pragma unroll
            for (int j = 0; j < 4; j++)
                atomicAdd(&orow[tx * 4 + j], acc[i][j] * wt);
        }
    }
}

// ---------------- launch ---------------------------------------------------
extern "C" void kernel_launch(void* const* d_in, const int* in_sizes, int n_in,
                              void* d_out, int out_size) {
    const float* x  = (const float*)d_in[0];
    const float* wg = (const float*)d_in[1];
    const float* w0 = (const float*)d_in[2];
    const float* w1 = (const float*)d_in[3];
    const float* wo = (const float*)d_in[4];
    float* out = (float*)d_out;

    zero_out_kernel<<<512, 256>>>((float4*)out, out_size / 4);
    zero_meta_kernel<<<1, 32>>>();
    gate_kernel<<<T_TOK / 8, 256>>>(x, wg);
    count_kernel<<<CAP / 256, 256>>>();
    scan_kernel<<<1, 1>>>();
    scatter_kernel<<<CAP / 256, 256>>>();
    gemm1_kernel<<<dim3(MAX_TILES, M_DIM / BN), 256>>>(x, w0, w1);
    gemm2_kernel<<<dim3(MAX_TILES, D_DIM / BN), 256>>>(wo, out);
}

// round 11
// speedup vs baseline: 3.2359x; 3.2359x over previous
#include <cuda_runtime.h>
#include <cuda_bf16.h>
#include <math.h>
#include <stdint.h>

#define T_TOK   32768
#define D_DIM   512
#define E_EXP   16
#define M_DIM   1024
#define CAP     (T_TOK * 2)               // 65536 bucket slots
#define BM      128                       // block M tile
#define NT      (CAP / BM + E_EXP)        // 528 max tiles

#define G1_AS   40    // A smem row stride (bf16 elems): 80B -> LDSM conflict-free
#define G1_BS   72    // gemm1 B row stride: 144B
#define G2_BS   136   // gemm2 B row stride: 272B

// ---------------- static device scratch (no allocs) ------------------------
__device__ int   g_top_idx[CAP];
__device__ float g_top_w[CAP];
__device__ int   g_counts[E_EXP];
__device__ int   g_offsets[E_EXP + 1];
__device__ int   g_fill[E_EXP];
__device__ int   g_btok[CAP];
__device__ float g_bw[CAP];
__device__ int   g_tile_e[NT];
__device__ int   g_tile_row[NT];
__device__ int   g_ntiles;
__device__ float g_h[(size_t)(CAP + BM) * M_DIM];   // 268 MB fp32 h (+pad tile)

// ---------------- PTX helpers ----------------------------------------------
__device__ __forceinline__ uint32_t smem_u32(const void* p) {
    uint32_t a;
    asm("{ .reg .u64 t; cvta.to.shared.u64 t, %1; cvt.u32.u64 %0, t; }" : "=r"(a) : "l"(p));
    return a;
}
__device__ __forceinline__ void ldsm_x4(uint32_t* r, uint32_t addr) {
    asm volatile("ldmatrix.sync.aligned.m8n8.x4.shared.b16 {%0,%1,%2,%3}, [%4];"
                 : "=r"(r[0]), "=r"(r[1]), "=r"(r[2]), "=r"(r[3]) : "r"(addr));
}
__device__ __forceinline__ void ldsm_x4_t(uint32_t* r, uint32_t addr) {
    asm volatile("ldmatrix.sync.aligned.m8n8.x4.trans.shared.b16 {%0,%1,%2,%3}, [%4];"
                 : "=r"(r[0]), "=r"(r[1]), "=r"(r[2]), "=r"(r[3]) : "r"(addr));
}
__device__ __forceinline__ void mma_bf16(float* c, const uint32_t* a, const uint32_t* b) {
    asm volatile("mma.sync.aligned.m16n8k16.row.col.f32.bf16.bf16.f32 "
                 "{%0,%1,%2,%3}, {%4,%5,%6,%7}, {%8,%9}, {%0,%1,%2,%3};"
                 : "+f"(c[0]), "+f"(c[1]), "+f"(c[2]), "+f"(c[3])
                 : "r"(a[0]), "r"(a[1]), "r"(a[2]), "r"(a[3]), "r"(b[0]), "r"(b[1]));
}
__device__ __forceinline__ void split2(float ax, float ay,
                                       __nv_bfloat162* hh, __nv_bfloat162* ll) {
    __nv_bfloat16 hx = __float2bfloat16(ax), hy = __float2bfloat16(ay);
    hh->x = hx; hh->y = hy;
    ll->x = __float2bfloat16(ax - __bfloat162float(hx));
    ll->y = __float2bfloat16(ay - __bfloat162float(hy));
}

// ---------------- small kernels --------------------------------------------
__global__ void zero_out_kernel(float4* out, int n4) {
    int stride = gridDim.x * blockDim.x;
    for (int i = blockIdx.x * blockDim.x + threadIdx.x; i < n4; i += stride)
        out[i] = make_float4(0.f, 0.f, 0.f, 0.f);
}
__global__ void zero_meta_kernel() {
    int t = threadIdx.x;
    if (t < E_EXP) { g_counts[t] = 0; g_fill[t] = 0; }
}

__global__ void gate_kernel(const float* __restrict__ x, const float* __restrict__ wg) {
    __shared__ float s_wg[D_DIM * 17];
    int tid = threadIdx.x;
    for (int i = tid; i < D_DIM * E_EXP; i += blockDim.x)
        s_wg[(i >> 4) * 17 + (i & 15)] = wg[i];
    __syncthreads();
    int warp = tid >> 5, lane = tid & 31;
    int tok = blockIdx.x * 8 + warp;
    if (tok >= T_TOK) return;
    float acc[E_EXP];
#pragma unroll
    for (int e = 0; e < E_EXP; e++) acc[e] = 0.f;
    const float* xr = x + (size_t)tok * D_DIM;
    for (int d = lane; d < D_DIM; d += 32) {
        float xv = xr[d];
        const float* wrow = &s_wg[d * 17];
#pragma unroll
        for (int e = 0; e < E_EXP; e++) acc[e] += xv * wrow[e];
    }
#pragma unroll
    for (int e = 0; e < E_EXP; e++) {
#pragma unroll
        for (int o = 16; o > 0; o >>= 1)
            acc[e] += __shfl_xor_sync(0xffffffffu, acc[e], o);
    }
    if (lane == 0) {
        int i0 = -1, i1 = -1;
        float v0 = -INFINITY, v1 = -INFINITY;
#pragma unroll
        for (int e = 0; e < E_EXP; e++) {
            float v = acc[e];
            if (v > v0) { v1 = v0; i1 = i0; v0 = v; i0 = e; }
            else if (v > v1) { v1 = v; i1 = e; }
        }
        float e1 = expf(v1 - v0);
        float inv = 1.f / (1.f + e1);
        g_top_idx[tok * 2]     = i0;
        g_top_idx[tok * 2 + 1] = i1;
        g_top_w[tok * 2]       = inv;
        g_top_w[tok * 2 + 1]   = e1 * inv;
    }
}

__global__ void count_kernel() {
    int i = blockIdx.x * blockDim.x + threadIdx.x;
    if (i < CAP) atomicAdd(&g_counts[g_top_idx[i]], 1);
}
__global__ void scan_kernel() {
    int s = 0, t = 0;
    for (int e = 0; e < E_EXP; e++) {
        g_offsets[e] = s;
        int c = g_counts[e];
        for (int r = 0; r < c; r += BM) { g_tile_e[t] = e; g_tile_row[t] = r; t++; }
        s += c;
    }
    g_offsets[E_EXP] = s;
    g_ntiles = t;
}
__global__ void scatter_kernel() {
    int i = blockIdx.x * blockDim.x + threadIdx.x;
    if (i < CAP) {
        int e = g_top_idx[i];
        int pos = atomicAdd(&g_fill[e], 1);
        int dst = g_offsets[e] + pos;
        g_btok[dst] = i >> 1;
        g_bw[dst]   = g_top_w[i];
    }
}

// ======== GEMM1 (mma.sync bf16x3): h = silu(X@w0) * (X@w1) ================
// block: 128 rows x 64 cols (of BOTH w0 and w1), 8 warps (warp tile 32x32x2)
__global__ void __launch_bounds__(256) gemm1_mma(
        const float* __restrict__ x,
        const float* __restrict__ w0,
        const float* __restrict__ w1) {
    if ((int)blockIdx.x >= g_ntiles) return;
    __shared__ __align__(16) __nv_bfloat16 sAh[128 * G1_AS];
    __shared__ __align__(16) __nv_bfloat16 sAl[128 * G1_AS];
    __shared__ __align__(16) __nv_bfloat16 sBh[2][32 * G1_BS];
    __shared__ __align__(16) __nv_bfloat16 sBl[2][32 * G1_BS];
    __shared__ int sTok[128];

    const int tid = threadIdx.x, lane = tid & 31, wid = tid >> 5;
    int e    = g_tile_e[blockIdx.x];
    int off  = g_offsets[e];
    int n_e  = g_offsets[e + 1] - off;
    int row0 = g_tile_row[blockIdx.x];
    int y    = blockIdx.y;

    if (tid < 128) { int r = row0 + tid; sTok[tid] = g_btok[off + (r < n_e ? r : 0)]; }
    __syncthreads();

    const float* wb0 = w0 + (size_t)e * D_DIM * M_DIM + y * 64;
    const float* wb1 = w1 + (size_t)e * D_DIM * M_DIM + y * 64;

    // slot decode (regs): A 2048 float2 slots, B 2048 (w0 first 1024, w1 next)
    float2 pA[8], pB[8];
#define G1_LOADA(kb_) { _Pragma("unroll") \
    for (int it = 0; it < 8; it++) { int s = tid + it * 256; \
        pA[it] = *(const float2*)(x + (size_t)sTok[s >> 4] * D_DIM + (kb_) + (s & 15) * 2); } }
#define G1_LOADB(kb_) { _Pragma("unroll") \
    for (int it = 0; it < 8; it++) { int s = tid + it * 256; int s2 = s & 1023; \
        const float* wp = (it < 4) ? wb0 : wb1; \
        pB[it] = *(const float2*)(wp + (size_t)((kb_) + (s2 >> 5)) * M_DIM + (s2 & 31) * 2); } }
#define G1_STORE() { _Pragma("unroll") \
    for (int it = 0; it < 8; it++) { int s = tid + it * 256; \
        __nv_bfloat162 hh, ll; split2(pA[it].x, pA[it].y, &hh, &ll); \
        int o = (s >> 4) * G1_AS + (s & 15) * 2; \
        *(__nv_bfloat162*)(sAh + o) = hh; *(__nv_bfloat162*)(sAl + o) = ll; } \
    _Pragma("unroll") \
    for (int it = 0; it < 8; it++) { int s = tid + it * 256; int mat = it >> 2; int s2 = s & 1023; \
        __nv_bfloat162 hh, ll; split2(pB[it].x, pB[it].y, &hh, &ll); \
        int o = (s2 >> 5) * G1_BS + (s2 & 31) * 2; \
        *(__nv_bfloat162*)(sBh[mat] + o) = hh; *(__nv_bfloat162*)(sBl[mat] + o) = ll; } }

    float u[2][4][4], v[2][4][4];
#pragma unroll
    for (int a = 0; a < 2; a++)
#pragma unroll
        for (int b = 0; b < 4; b++)
#pragma unroll
            for (int c = 0; c < 4; c++) { u[a][b][c] = 0.f; v[a][b][c] = 0.f; }

    uint32_t bAh = smem_u32(sAh), bAl = smem_u32(sAl);
    uint32_t bBh0 = smem_u32(sBh[0]), bBh1 = smem_u32(sBh[1]);
    uint32_t bBl0 = smem_u32(sBl[0]), bBl1 = smem_u32(sBl[1]);
    const int warp_m = wid >> 1, warp_n = wid & 1;
    const int lr = lane & 15, lc = (lane >> 4) << 3;
    const int browb = (lane & 7) + ((lane >> 3) & 1) * 8;
    const int bcolb = warp_n * 32 + ((lane >> 4) & 1) * 8;

    G1_LOADA(0); G1_LOADB(0);
    for (int kb = 0; kb < D_DIM; kb += 32) {
        G1_STORE();
        __syncthreads();
        if (kb + 32 < D_DIM) { G1_LOADA(kb + 32); G1_LOADB(kb + 32); }
#pragma unroll
        for (int ks = 0; ks < 2; ks++) {
            uint32_t ah[2][4], al[2][4];
#pragma unroll
            for (int mb = 0; mb < 2; mb++) {
                uint32_t o = (uint32_t)((warp_m * 32 + mb * 16 + lr) * G1_AS + ks * 16 + lc) * 2;
                ldsm_x4(ah[mb], bAh + o);
                ldsm_x4(al[mb], bAl + o);
            }
#pragma unroll
            for (int g = 0; g < 2; g++) {
                uint32_t bh0[4], bl0[4], bh1[4], bl1[4];
                uint32_t o = (uint32_t)((ks * 16 + browb) * G1_BS + bcolb + g * 16) * 2;
                ldsm_x4_t(bh0, bBh0 + o); ldsm_x4_t(bl0, bBl0 + o);
                ldsm_x4_t(bh1, bBh1 + o); ldsm_x4_t(bl1, bBl1 + o);
#pragma unroll
                for (int mb = 0; mb < 2; mb++)
#pragma unroll
                    for (int j = 0; j < 2; j++) {
                        int nb = g * 2 + j;
                        mma_bf16(u[mb][nb], ah[mb], bh0 + 2 * j);
                        mma_bf16(u[mb][nb], ah[mb], bl0 + 2 * j);
                        mma_bf16(u[mb][nb], al[mb], bh0 + 2 * j);
                        mma_bf16(v[mb][nb], ah[mb], bh1 + 2 * j);
                        mma_bf16(v[mb][nb], ah[mb], bl1 + 2 * j);
                        mma_bf16(v[mb][nb], al[mb], bh1 + 2 * j);
                    }
            }
        }
        __syncthreads();
    }

    // epilogue: h = silu(u) * v -> fp32 g_h
    const int lr4 = lane >> 2, lc2 = (lane & 3) * 2;
#pragma unroll
    for (int mb = 0; mb < 2; mb++)
#pragma unroll
        for (int nb = 0; nb < 4; nb++) {
            int rl   = warp_m * 32 + mb * 16 + lr4;
            int mcol = y * 64 + warp_n * 32 + nb * 8 + lc2;
#pragma unroll
            for (int hh = 0; hh < 2; hh++) {
                int r = rl + hh * 8;
                if (row0 + r < n_e) {
                    float u0 = u[mb][nb][2 * hh], u1 = u[mb][nb][2 * hh + 1];
                    float v0 = v[mb][nb][2 * hh], v1 = v[mb][nb][2 * hh + 1];
                    float h0 = u0 / (1.f + __expf(-u0)) * v0;
                    float h1 = u1 / (1.f + __expf(-u1)) * v1;
                    *(float2*)(g_h + (size_t)(off + row0 + r) * M_DIM + mcol) = make_float2(h0, h1);
                }
            }
        }
#undef G1_LOADA
#undef G1_LOADB
#undef G1_STORE
}

// ======== GEMM2 (mma.sync bf16x3): out += wt * (h @ wo) ===================
// block: 128 rows x 128 cols, 8 warps (warp tile 32x64)
__global__ void __launch_bounds__(256) gemm2_mma(
        const float* __restrict__ wo,
        float* __restrict__ out) {
    if ((int)blockIdx.x >= g_ntiles) return;
    __shared__ __align__(16) __nv_bfloat16 sAh[128 * G1_AS];
    __shared__ __align__(16) __nv_bfloat16 sAl[128 * G1_AS];
    __shared__ __align__(16) __nv_bfloat16 sBh[32 * G2_BS];
    __shared__ __align__(16) __nv_bfloat16 sBl[32 * G2_BS];
    __shared__ int   sTok[128];
    __shared__ float sWt[128];

    const int tid = threadIdx.x, lane = tid & 31, wid = tid >> 5;
    int e    = g_tile_e[blockIdx.x];
    int off  = g_offsets[e];
    int n_e  = g_offsets[e + 1] - off;
    int row0 = g_tile_row[blockIdx.x];
    int y    = blockIdx.y;
    int rows_in_tile = n_e - row0;

    if (tid < 128) {
        int r = row0 + tid;
        int src = off + (r < n_e ? r : 0);
        sTok[tid] = g_btok[src];
        sWt[tid]  = g_bw[src];
    }
    __syncthreads();

    const float* Ab = g_h + (size_t)(off + row0) * M_DIM;   // pad tile keeps OOB rows in-bounds
    const float* Bb = wo + (size_t)e * M_DIM * D_DIM + y * 128;

    float2 pA[8], pB[8];
#define G2_LOADA(kb_) { _Pragma("unroll") \
    for (int it = 0; it < 8; it++) { int s = tid + it * 256; \
        pA[it] = *(const float2*)(Ab + (size_t)(s >> 4) * M_DIM + (kb_) + (s & 15) * 2); } }
#define G2_LOADB(kb_) { _Pragma("unroll") \
    for (int it = 0; it < 8; it++) { int s = tid + it * 256; \
        pB[it] = *(const float2*)(Bb + (size_t)((kb_) + (s >> 6)) * D_DIM + (s & 63) * 2); } }
#define G2_STORE() { _Pragma("unroll") \
    for (int it = 0; it < 8; it++) { int s = tid + it * 256; \
        __nv_bfloat162 hh, ll; split2(pA[it].x, pA[it].y, &hh, &ll); \
        int o = (s >> 4) * G1_AS + (s & 15) * 2; \
        *(__nv_bfloat162*)(sAh + o) = hh; *(__nv_bfloat162*)(sAl + o) = ll; } \
    _Pragma("unroll") \
    for (int it = 0; it < 8; it++) { int s = tid + it * 256; \
        __nv_bfloat162 hh, ll; split2(pB[it].x, pB[it].y, &hh, &ll); \
        int o = (s >> 6) * G2_BS + (s & 63) * 2; \
        *(__nv_bfloat162*)(sBh + o) = hh; *(__nv_bfloat162*)(sBl + o) = ll; } }

    float c[2][8][4];
#pragma unroll
    for (int a = 0; a < 2; a++)
#pragma unroll
        for (int b = 0; b < 8; b++)
#pragma unroll
            for (int q = 0; q < 4; q++) c[a][b][q] = 0.f;

    uint32_t bAh = smem_u32(sAh), bAl = smem_u32(sAl);
    uint32_t bBh = smem_u32(sBh), bBl = smem_u32(sBl);
    const int warp_m = wid >> 1, warp_n = wid & 1;
    const int lr = lane & 15, lc = (lane >> 4) << 3;
    const int browb = (lane & 7) + ((lane >> 3) & 1) * 8;
    const int bcolb = warp_n * 64 + ((lane >> 4) & 1) * 8;

    G2_LOADA(0); G2_LOADB(0);
    for (int kb = 0; kb < M_DIM; kb += 32) {
        G2_STORE();
        __syncthreads();
        if (kb + 32 < M_DIM) { G2_LOADA(kb + 32); G2_LOADB(kb + 32); }
#pragma unroll
        for (int ks = 0; ks < 2; ks++) {
            uint32_t ah[2][4], al[2][4];
#pragma unroll
            for (int mb = 0; mb < 2; mb++) {
                uint32_t o = (uint32_t)((warp_m * 32 + mb * 16 + lr) * G1_AS + ks * 16 + lc) * 2;
                ldsm_x4(ah[mb], bAh + o);
                ldsm_x4(al[mb], bAl + o);
            }
#pragma unroll
            for (int g = 0; g < 4; g++) {
                uint32_t bh[4], bl[4];
                uint32_t o = (uint32_t)((ks * 16 + browb) * G2_BS + bcolb + g * 16) * 2;
                ldsm_x4_t(bh, bBh + o);
                ldsm_x4_t(bl, bBl + o);
#pragma unroll
                for (int mb = 0; mb < 2; mb++)
#pragma unroll
                    for (int j = 0; j < 2; j++) {
                        int nb = g * 2 + j;
                        mma_bf16(c[mb][nb], ah[mb], bh + 2 * j);
                        mma_bf16(c[mb][nb], ah[mb], bl + 2 * j);
                        mma_bf16(c[mb][nb], al[mb], bh + 2 * j);
                    }
            }
        }
        __syncthreads();
    }

    const int lr4 = lane >> 2, lc2 = (lane & 3) * 2;
#pragma unroll
    for (int mb = 0; mb < 2; mb++)
#pragma unroll
        for (int nb = 0; nb < 8; nb++) {
            int rl  = warp_m * 32 + mb * 16 + lr4;
            int col = y * 128 + warp_n * 64 + nb * 8 + lc2;
#pragma unroll
            for (int hh = 0; hh < 2; hh++) {
                int r = rl + hh * 8;
                if (r < rows_in_tile) {
                    float wt = sWt[r];
                    float* orow = out + (size_t)sTok[r] * D_DIM + col;
                    atomicAdd(&orow[0], wt * c[mb][nb][2 * hh]);
                    atomicAdd(&orow[1], wt * c[mb][nb][2 * hh + 1]);
                }
            }
        }
#undef G2_LOADA
#undef G2_LOADB
#undef G2_STORE
}

// ---------------- launch ---------------------------------------------------
extern "C" void kernel_launch(void* const* d_in, const int* in_sizes, int n_in,
                              void* d_out, int out_size) {
    const float* x  = (const float*)d_in[0];
    const float* wg = (const float*)d_in[1];
    const float* w0 = (const float*)d_in[2];
    const float* w1 = (const float*)d_in[3];
    const float* wo = (const float*)d_in[4];
    float* out = (float*)d_out;

    zero_out_kernel<<<512, 256>>>((float4*)out, out_size / 4);
    zero_meta_kernel<<<1, 32>>>();
    gate_kernel<<<T_TOK / 8, 256>>>(x, wg);
    count_kernel<<<CAP / 256, 256>>>();
    scan_kernel<<<1, 1>>>();
    scatter_kernel<<<CAP / 256, 256>>>();
    gemm1_mma<<<dim3(NT, M_DIM / 64), 256>>>(x, w0, w1);
    gemm2_mma<<<dim3(NT, D_DIM / 128), 256>>>(wo, out);
}

// round 16
// speedup vs baseline: 4.2166x; 1.3031x over previous
#include <cuda_runtime.h>
#include <cuda_bf16.h>
#include <math.h>
#include <stdint.h>

#define T_TOK   32768
#define D_DIM   512
#define E_EXP   16
#define M_DIM   1024
#define CAP     (T_TOK * 2)               // 65536 bucket slots
#define BM      128                       // block M tile
#define NT      (CAP / BM + E_EXP)        // 528 max tiles

#define G1_AS   40    // A smem row stride (bf16 elems): 80B -> LDSM conflict-free
#define G1_BS   72    // gemm1 B row stride: 144B
#define G2_BS   136   // gemm2 B row stride: 272B

// gemm1 per-stage smem layout (bf16 elems)
#define S1_AH   0
#define S1_AL   5120
#define S1_B0H  10240
#define S1_B0L  12544
#define S1_B1H  14848
#define S1_B1L  17152
#define S1_STG  19456
// gemm2 per-stage smem layout
#define S2_AH   0
#define S2_AL   5120
#define S2_BH   10240
#define S2_BL   14592
#define S2_STG  18944

// ---------------- static device scratch (no allocs) ------------------------
__device__ int   g_top_idx[CAP];
__device__ float g_top_w[CAP];
__device__ int   g_counts[E_EXP];
__device__ int   g_offsets[E_EXP + 1];
__device__ int   g_fill[E_EXP];
__device__ int   g_btok[CAP];
__device__ int   g_inv[CAP];              // slot of routing entry i (= tok*2+k)
__device__ int   g_tile_e[NT];
__device__ int   g_tile_row[NT];
__device__ int   g_ntiles;
// bf16 hi/lo planes (pre-split)
__device__ __nv_bfloat16 g_xh[(size_t)T_TOK * D_DIM];
__device__ __nv_bfloat16 g_xl[(size_t)T_TOK * D_DIM];
__device__ __nv_bfloat16 g_w0h[(size_t)E_EXP * D_DIM * M_DIM];
__device__ __nv_bfloat16 g_w0l[(size_t)E_EXP * D_DIM * M_DIM];
__device__ __nv_bfloat16 g_w1h[(size_t)E_EXP * D_DIM * M_DIM];
__device__ __nv_bfloat16 g_w1l[(size_t)E_EXP * D_DIM * M_DIM];
__device__ __nv_bfloat16 g_woh[(size_t)E_EXP * M_DIM * D_DIM];
__device__ __nv_bfloat16 g_wol[(size_t)E_EXP * M_DIM * D_DIM];
__device__ __nv_bfloat16 g_hh[(size_t)(CAP + BM) * M_DIM];    // h hi plane (+pad tile)
__device__ __nv_bfloat16 g_hl[(size_t)(CAP + BM) * M_DIM];    // h lo plane
__device__ float g_o2[(size_t)(CAP + BM) * D_DIM];            // per-slot gemm2 result

// ---------------- PTX helpers ----------------------------------------------
__device__ __forceinline__ uint32_t smem_u32(const void* p) {
    uint32_t a;
    asm("{ .reg .u64 t; cvta.to.shared.u64 t, %1; cvt.u32.u64 %0, t; }" : "=r"(a) : "l"(p));
    return a;
}
__device__ __forceinline__ void ldsm_x4(uint32_t* r, uint32_t addr) {
    asm volatile("ldmatrix.sync.aligned.m8n8.x4.shared.b16 {%0,%1,%2,%3}, [%4];"
                 : "=r"(r[0]), "=r"(r[1]), "=r"(r[2]), "=r"(r[3]) : "r"(addr));
}
__device__ __forceinline__ void ldsm_x4_t(uint32_t* r, uint32_t addr) {
    asm volatile("ldmatrix.sync.aligned.m8n8.x4.trans.shared.b16 {%0,%1,%2,%3}, [%4];"
                 : "=r"(r[0]), "=r"(r[1]), "=r"(r[2]), "=r"(r[3]) : "r"(addr));
}
__device__ __forceinline__ void mma_bf16(float* c, const uint32_t* a, const uint32_t* b) {
    asm volatile("mma.sync.aligned.m16n8k16.row.col.f32.bf16.bf16.f32 "
                 "{%0,%1,%2,%3}, {%4,%5,%6,%7}, {%8,%9}, {%0,%1,%2,%3};"
                 : "+f"(c[0]), "+f"(c[1]), "+f"(c[2]), "+f"(c[3])
                 : "r"(a[0]), "r"(a[1]), "r"(a[2]), "r"(a[3]), "r"(b[0]), "r"(b[1]));
}
#define CP16(dst, src) \
    asm volatile("cp.async.cg.shared.global [%0], [%1], 16;" :: "r"(dst), "l"(src))
#define CP_COMMIT() asm volatile("cp.async.commit_group;" ::: "memory")
#define CP_WAIT1()  asm volatile("cp.async.wait_group 1;" ::: "memory")
#define CP_WAIT0()  asm volatile("cp.async.wait_group 0;" ::: "memory")

__device__ __forceinline__ void split2(float ax, float ay,
                                       __nv_bfloat162* hh, __nv_bfloat162* ll) {
    __nv_bfloat16 hx = __float2bfloat16(ax), hy = __float2bfloat16(ay);
    hh->x = hx; hh->y = hy;
    ll->x = __float2bfloat16(ax - __bfloat162float(hx));
    ll->y = __float2bfloat16(ay - __bfloat162float(hy));
}

// ---------------- small kernels --------------------------------------------
__global__ void zero_meta_kernel() {
    int t = threadIdx.x;
    if (t < E_EXP) { g_counts[t] = 0; g_fill[t] = 0; }
}

__global__ void gate_kernel(const float* __restrict__ x, const float* __restrict__ wg) {
    __shared__ float s_wg[D_DIM * 17];
    int tid = threadIdx.x;
    for (int i = tid; i < D_DIM * E_EXP; i += blockDim.x)
        s_wg[(i >> 4) * 17 + (i & 15)] = wg[i];
    __syncthreads();
    int warp = tid >> 5, lane = tid & 31;
    int tok = blockIdx.x * 8 + warp;
    if (tok >= T_TOK) return;
    float acc[E_EXP];
#pragma unroll
    for (int e = 0; e < E_EXP; e++) acc[e] = 0.f;
    const float* xr = x + (size_t)tok * D_DIM;
    for (int d = lane; d < D_DIM; d += 32) {
        float xv = xr[d];
        const float* wrow = &s_wg[d * 17];
#pragma unroll
        for (int e = 0; e < E_EXP; e++) acc[e] += xv * wrow[e];
    }
#pragma unroll
    for (int e = 0; e < E_EXP; e++) {
#pragma unroll
        for (int o = 16; o > 0; o >>= 1)
            acc[e] += __shfl_xor_sync(0xffffffffu, acc[e], o);
    }
    if (lane == 0) {
        int i0 = -1, i1 = -1;
        float v0 = -INFINITY, v1 = -INFINITY;
#pragma unroll
        for (int e = 0; e < E_EXP; e++) {
            float v = acc[e];
            if (v > v0) { v1 = v0; i1 = i0; v0 = v; i0 = e; }
            else if (v > v1) { v1 = v; i1 = e; }
        }
        float e1 = expf(v1 - v0);
        float inv = 1.f / (1.f + e1);
        g_top_idx[tok * 2]     = i0;
        g_top_idx[tok * 2 + 1] = i1;
        g_top_w[tok * 2]       = inv;
        g_top_w[tok * 2 + 1]   = e1 * inv;
    }
}

__global__ void count_kernel() {
    int i = blockIdx.x * blockDim.x + threadIdx.x;
    if (i < CAP) atomicAdd(&g_counts[g_top_idx[i]], 1);
}
__global__ void scan_kernel() {
    int s = 0, t = 0;
    for (int e = 0; e < E_EXP; e++) {
        g_offsets[e] = s;
        int c = g_counts[e];
        for (int r = 0; r < c; r += BM) { g_tile_e[t] = e; g_tile_row[t] = r; t++; }
        s += c;
    }
    g_offsets[E_EXP] = s;
    g_ntiles = t;
}
__global__ void scatter_kernel() {
    int i = blockIdx.x * blockDim.x + threadIdx.x;
    if (i < CAP) {
        int e = g_top_idx[i];
        int pos = atomicAdd(&g_fill[e], 1);
        int dst = g_offsets[e] + pos;
        g_btok[dst] = i >> 1;
        g_inv[i]    = dst;
    }
}

// pre-split fp32 -> bf16 hi/lo planes (vector-4)
__global__ void conv_split_kernel(const float4* __restrict__ src,
                                  __nv_bfloat162* __restrict__ dh,
                                  __nv_bfloat162* __restrict__ dl, int n4) {
    int i = blockIdx.x * blockDim.x + threadIdx.x;
    if (i >= n4) return;
    float4 v = src[i];
    __nv_bfloat162 h0, l0, h1, l1;
    split2(v.x, v.y, &h0, &l0);
    split2(v.z, v.w, &h1, &l1);
    dh[i * 2] = h0; dh[i * 2 + 1] = h1;
    dl[i * 2] = l0; dl[i * 2 + 1] = l1;
}

// ======== GEMM1 (cp.async 2-stage + mma bf16x3): h = silu(X@w0)*(X@w1) =====
// block 128 rows x 64 cols of both w0/w1; 8 warps (warp 32m x 32n x 2 mats)
__global__ void __launch_bounds__(256, 2) gemm1_mma() {
    if ((int)blockIdx.x >= g_ntiles) return;
    extern __shared__ __nv_bfloat16 dsm[];
    __shared__ int sTok[128];

    const int tid = threadIdx.x, lane = tid & 31, wid = tid >> 5;
    int e    = g_tile_e[blockIdx.x];
    int off  = g_offsets[e];
    int n_e  = g_offsets[e + 1] - off;
    int row0 = g_tile_row[blockIdx.x];
    int y    = blockIdx.y;

    if (tid < 128) { int r = row0 + tid; sTok[tid] = g_btok[off + (r < n_e ? r : 0)]; }
    __syncthreads();

    size_t wofs = (size_t)e * D_DIM * M_DIM + (size_t)y * 64;
    const __nv_bfloat16* wp[4] = { g_w0h + wofs, g_w0l + wofs, g_w1h + wofs, g_w1l + wofs };
    uint32_t smb = smem_u32(dsm);

#define G1_ISSUE(it_) { \
    int kb = (it_) * 32; \
    uint32_t sb = smb + (uint32_t)((it_) & 1) * (S1_STG * 2); \
    _Pragma("unroll") \
    for (int i = 0; i < 4; i++) { int lin = tid + i * 256; int pl = lin >> 9; \
        int r = (lin >> 2) & 127; int q = lin & 3; \
        const __nv_bfloat16* src = (pl ? g_xl : g_xh) + (size_t)sTok[r] * D_DIM + kb + q * 8; \
        CP16(sb + (uint32_t)(pl * 5120 + r * G1_AS + q * 8) * 2, src); } \
    _Pragma("unroll") \
    for (int i = 0; i < 4; i++) { int lin = tid + i * 256; int sel = lin >> 8; \
        int r = (lin >> 3) & 31; int q = lin & 7; \
        const __nv_bfloat16* src = wp[sel] + (size_t)(kb + r) * M_DIM + q * 8; \
        CP16(sb + (uint32_t)(S1_B0H + sel * 2304 + r * G1_BS + q * 8) * 2, src); } \
    CP_COMMIT(); }

    float u[2][4][4], v[2][4][4];
#pragma unroll
    for (int a = 0; a < 2; a++)
#pragma unroll
        for (int b = 0; b < 4; b++)
#pragma unroll
            for (int c = 0; c < 4; c++) { u[a][b][c] = 0.f; v[a][b][c] = 0.f; }

    const int warp_m = wid >> 1, warp_n = wid & 1;
    const int lr = lane & 15, lc = (lane >> 4) << 3;
    const int browb = (lane & 7) + ((lane >> 3) & 1) * 8;
    const int bcolb = warp_n * 32 + ((lane >> 4) & 1) * 8;

    G1_ISSUE(0);
    for (int it = 0; it < 16; it++) {
        if (it + 1 < 16) { G1_ISSUE(it + 1); CP_WAIT1(); } else { CP_WAIT0(); }
        __syncthreads();
        uint32_t sb = smb + (uint32_t)(it & 1) * (S1_STG * 2);
#pragma unroll
        for (int ks = 0; ks < 2; ks++) {
            uint32_t ah[2][4], al[2][4];
#pragma unroll
            for (int mb = 0; mb < 2; mb++) {
                uint32_t o = (uint32_t)((warp_m * 32 + mb * 16 + lr) * G1_AS + ks * 16 + lc) * 2;
                ldsm_x4(ah[mb], sb + S1_AH * 2 + o);
                ldsm_x4(al[mb], sb + S1_AL * 2 + o);
            }
#pragma unroll
            for (int g = 0; g < 2; g++) {
                uint32_t bh0[4], bl0[4], bh1[4], bl1[4];
                uint32_t o = (uint32_t)((ks * 16 + browb) * G1_BS + bcolb + g * 16) * 2;
                ldsm_x4_t(bh0, sb + S1_B0H * 2 + o);
                ldsm_x4_t(bl0, sb + S1_B0L * 2 + o);
                ldsm_x4_t(bh1, sb + S1_B1H * 2 + o);
                ldsm_x4_t(bl1, sb + S1_B1L * 2 + o);
#pragma unroll
                for (int mb = 0; mb < 2; mb++)
#pragma unroll
                    for (int j = 0; j < 2; j++) {
                        int nb = g * 2 + j;
                        mma_bf16(u[mb][nb], ah[mb], bh0 + 2 * j);
                        mma_bf16(u[mb][nb], ah[mb], bl0 + 2 * j);
                        mma_bf16(u[mb][nb], al[mb], bh0 + 2 * j);
                        mma_bf16(v[mb][nb], ah[mb], bh1 + 2 * j);
                        mma_bf16(v[mb][nb], ah[mb], bl1 + 2 * j);
                        mma_bf16(v[mb][nb], al[mb], bh1 + 2 * j);
                    }
            }
        }
        __syncthreads();
    }

    // epilogue: h = silu(u)*v -> bf16 hi/lo planes
    const int lr4 = lane >> 2, lc2 = (lane & 3) * 2;
#pragma unroll
    for (int mb = 0; mb < 2; mb++)
#pragma unroll
        for (int nb = 0; nb < 4; nb++) {
            int rl   = warp_m * 32 + mb * 16 + lr4;
            int mcol = y * 64 + warp_n * 32 + nb * 8 + lc2;
#pragma unroll
            for (int hh = 0; hh < 2; hh++) {
                int r = rl + hh * 8;
                if (row0 + r < n_e) {
                    float u0 = u[mb][nb][2 * hh], u1 = u[mb][nb][2 * hh + 1];
                    float v0 = v[mb][nb][2 * hh], v1 = v[mb][nb][2 * hh + 1];
                    float h0 = u0 / (1.f + __expf(-u0)) * v0;
                    float h1 = u1 / (1.f + __expf(-u1)) * v1;
                    __nv_bfloat162 hh2, ll2;
                    split2(h0, h1, &hh2, &ll2);
                    size_t p = (size_t)(off + row0 + r) * M_DIM + mcol;
                    *(__nv_bfloat162*)(g_hh + p) = hh2;
                    *(__nv_bfloat162*)(g_hl + p) = ll2;
                }
            }
        }
#undef G1_ISSUE
}

// ======== GEMM2 (cp.async 2-stage + mma bf16x3): o2 = h @ wo ==============
// block 128 rows x 128 cols; 8 warps (warp 32m x 64n)
__global__ void __launch_bounds__(256, 2) gemm2_mma() {
    if ((int)blockIdx.x >= g_ntiles) return;
    extern __shared__ __nv_bfloat16 dsm[];

    const int tid = threadIdx.x, lane = tid & 31, wid = tid >> 5;
    int e    = g_tile_e[blockIdx.x];
    int off  = g_offsets[e];
    int n_e  = g_offsets[e + 1] - off;
    int row0 = g_tile_row[blockIdx.x];
    int y    = blockIdx.y;
    int rows_in_tile = n_e - row0;

    const __nv_bfloat16* Ah = g_hh + (size_t)(off + row0) * M_DIM;   // pad tile keeps OOB safe
    const __nv_bfloat16* Al = g_hl + (size_t)(off + row0) * M_DIM;
    size_t wofs = (size_t)e * M_DIM * D_DIM + (size_t)y * 128;
    const __nv_bfloat16* Bh = g_woh + wofs;
    const __nv_bfloat16* Bl = g_wol + wofs;
    uint32_t smb = smem_u32(dsm);

#define G2_ISSUE(it_) { \
    int kb = (it_) * 32; \
    uint32_t sb = smb + (uint32_t)((it_) & 1) * (S2_STG * 2); \
    _Pragma("unroll") \
    for (int i = 0; i < 4; i++) { int lin = tid + i * 256; int pl = lin >> 9; \
        int r = (lin >> 2) & 127; int q = lin & 3; \
        const __nv_bfloat16* src = (pl ? Al : Ah) + (size_t)r * M_DIM + kb + q * 8; \
        CP16(sb + (uint32_t)(pl * 5120 + r * G1_AS + q * 8) * 2, src); } \
    _Pragma("unroll") \
    for (int i = 0; i < 4; i++) { int lin = tid + i * 256; int pl = lin >> 9; \
        int r = (lin >> 4) & 31; int q = lin & 15; \
        const __nv_bfloat16* src = (pl ? Bl : Bh) + (size_t)(kb + r) * D_DIM + q * 8; \
        CP16(sb + (uint32_t)(S2_BH + pl * 4352 + r * G2_BS + q * 8) * 2, src); } \
    CP_COMMIT(); }

    float c[2][8][4];
#pragma unroll
    for (int a = 0; a < 2; a++)
#pragma unroll
        for (int b = 0; b < 8; b++)
#pragma unroll
            for (int q = 0; q < 4; q++) c[a][b][q] = 0.f;

    const int warp_m = wid >> 1, warp_n = wid & 1;
    const int lr = lane & 15, lc = (lane >> 4) << 3;
    const int browb = (lane & 7) + ((lane >> 3) & 1) * 8;
    const int bcolb = warp_n * 64 + ((lane >> 4) & 1) * 8;

    G2_ISSUE(0);
    for (int it = 0; it < 32; it++) {
        if (it + 1 < 32) { G2_ISSUE(it + 1); CP_WAIT1(); } else { CP_WAIT0(); }
        __syncthreads();
        uint32_t sb = smb + (uint32_t)(it & 1) * (S2_STG * 2);
#pragma unroll
        for (int ks = 0; ks < 2; ks++) {
            uint32_t ah[2][4], al[2][4];
#pragma unroll
            for (int mb = 0; mb < 2; mb++) {
                uint32_t o = (uint32_t)((warp_m * 32 + mb * 16 + lr) * G1_AS + ks * 16 + lc) * 2;
                ldsm_x4(ah[mb], sb + S2_AH * 2 + o);
                ldsm_x4(al[mb], sb + S2_AL * 2 + o);
            }
#pragma unroll
            for (int g = 0; g < 4; g++) {
                uint32_t bh[4], bl[4];
                uint32_t o = (uint32_t)((ks * 16 + browb) * G2_BS + bcolb + g * 16) * 2;
                ldsm_x4_t(bh, sb + S2_BH * 2 + o);
                ldsm_x4_t(bl, sb + S2_BL * 2 + o);
#pragma unroll
                for (int mb = 0; mb < 2; mb++)
#pragma unroll
                    for (int j = 0; j < 2; j++) {
                        int nb = g * 2 + j;
                        mma_bf16(c[mb][nb], ah[mb], bh + 2 * j);
                        mma_bf16(c[mb][nb], ah[mb], bl + 2 * j);
                        mma_bf16(c[mb][nb], al[mb], bh + 2 * j);
                    }
            }
        }
        __syncthreads();
    }

    // epilogue: plain STG of per-slot rows (weights applied in combine)
    const int lr4 = lane >> 2, lc2 = (lane & 3) * 2;
#pragma unroll
    for (int mb = 0; mb < 2; mb++)
#pragma unroll
        for (int nb = 0; nb < 8; nb++) {
            int rl  = warp_m * 32 + mb * 16 + lr4;
            int col = y * 128 + warp_n * 64 + nb * 8 + lc2;
#pragma unroll
            for (int hh = 0; hh < 2; hh++) {
                int r = rl + hh * 8;
                if (r < rows_in_tile) {
                    *(float2*)(g_o2 + (size_t)(off + row0 + r) * D_DIM + col) =
                        make_float2(c[mb][nb][2 * hh], c[mb][nb][2 * hh + 1]);
                }
            }
        }
#undef G2_ISSUE
}

// ---------------- combine: out[t] = w0*o2[slot0] + w1*o2[slot1] ------------
__global__ void combine_kernel(float4* __restrict__ out) {
    int i = blockIdx.x * blockDim.x + threadIdx.x;    // T*D/4 threads
    int t  = i >> 7;                                  // D/4 = 128 float4 per token
    int d4 = (i & 127) << 2;
    int s0 = g_inv[t * 2], s1 = g_inv[t * 2 + 1];
    float w0 = g_top_w[t * 2], w1 = g_top_w[t * 2 + 1];
    float4 a = *(const float4*)(g_o2 + (size_t)s0 * D_DIM + d4);
    float4 b = *(const float4*)(g_o2 + (size_t)s1 * D_DIM + d4);
    out[i] = make_float4(w0 * a.x + w1 * b.x, w0 * a.y + w1 * b.y,
                         w0 * a.z + w1 * b.z, w0 * a.w + w1 * b.w);
}

// ---------------- launch ---------------------------------------------------
extern "C" void kernel_launch(void* const* d_in, const int* in_sizes, int n_in,
                              void* d_out, int out_size) {
    const float* x  = (const float*)d_in[0];
    const float* wg = (const float*)d_in[1];
    const float* w0 = (const float*)d_in[2];
    const float* w1 = (const float*)d_in[3];
    const float* wo = (const float*)d_in[4];
    float* out = (float*)d_out;

    cudaFuncSetAttribute(gemm1_mma, cudaFuncAttributeMaxDynamicSharedMemorySize, 2 * S1_STG * 2);
    cudaFuncSetAttribute(gemm2_mma, cudaFuncAttributeMaxDynamicSharedMemorySize, 2 * S2_STG * 2);

    __nv_bfloat162 *xh2, *xl2, *w0h2, *w0l2, *w1h2, *w1l2, *woh2, *wol2;
    cudaGetSymbolAddress((void**)&xh2,  g_xh);
    cudaGetSymbolAddress((void**)&xl2,  g_xl);
    cudaGetSymbolAddress((void**)&w0h2, g_w0h);
    cudaGetSymbolAddress((void**)&w0l2, g_w0l);
    cudaGetSymbolAddress((void**)&w1h2, g_w1h);
    cudaGetSymbolAddress((void**)&w1l2, g_w1l);
    cudaGetSymbolAddress((void**)&woh2, g_woh);
    cudaGetSymbolAddress((void**)&wol2, g_wol);

    zero_meta_kernel<<<1, 32>>>();
    gate_kernel<<<T_TOK / 8, 256>>>(x, wg);
    count_kernel<<<CAP / 256, 256>>>();
    scan_kernel<<<1, 1>>>();
    scatter_kernel<<<CAP / 256, 256>>>();

    const int nx4 = T_TOK * D_DIM / 4;                 // 4,194,304
    const int nw4 = E_EXP * D_DIM * M_DIM / 4;         // 2,097,152
    conv_split_kernel<<<nx4 / 256, 256>>>((const float4*)x,  xh2,  xl2,  nx4);
    conv_split_kernel<<<nw4 / 256, 256>>>((const float4*)w0, w0h2, w0l2, nw4);
    conv_split_kernel<<<nw4 / 256, 256>>>((const float4*)w1, w1h2, w1l2, nw4);
    conv_split_kernel<<<nw4 / 256, 256>>>((const float4*)wo, woh2, wol2, nw4);

    gemm1_mma<<<dim3(NT, M_DIM / 64), 256, 2 * S1_STG * 2>>>();
    gemm2_mma<<<dim3(NT, D_DIM / 128), 256, 2 * S2_STG * 2>>>();
    combine_kernel<<<(T_TOK * D_DIM / 4) / 256, 256>>>((float4*)out);
}